// round 2
// baseline (speedup 1.0000x reference)
#include <cuda_runtime.h>

#define B_ 128
#define T_ 128
#define D_ 2048
#define U_ 512

// ---- device scratch (no allocations allowed) ----
__device__ float g_xproj[(size_t)B_ * T_ * U_];   // 32 MB: x @ w_in + b
__device__ float g_H[B_ * U_];                    // current hidden state
__device__ float g_psum[B_ * 8];                  // LN partial sums per (row, colblock)
__device__ float g_psq[B_ * 8];                   // LN partial sum of squares
__device__ int   g_bar[16];                       // per-rowblock barrier counters

// =====================================================================
// Kernel 1: x_proj = x @ w_in + bias   (M=16384, K=2048, N=512) fp32
// classic 128x128x8 SIMT tiled SGEMM, 256 threads, 8x8 microtile
// =====================================================================
__global__ void __launch_bounds__(256) gemm_xproj(const float* __restrict__ X,
                                                  const float* __restrict__ W,
                                                  const float* __restrict__ bias) {
    __shared__ float As[8][128];   // As[k][m]
    __shared__ float Bs[8][128];   // Bs[k][n]

    const int tid = threadIdx.x;
    const int bn = blockIdx.x;       // 0..3   (N blocks of 128)
    const int bm = blockIdx.y;       // 0..127 (M blocks of 128)
    const int tx = tid & 15;         // n dir
    const int ty = tid >> 4;         // m dir

    const int aRow = tid >> 1;            // 0..127
    const int aCol = (tid & 1) * 4;       // 0 or 4
    const int wRow = tid >> 5;            // 0..7
    const int wCol = (tid & 31) * 4;      // 0..124

    const float* Xb = X + (size_t)bm * 128 * D_;
    const float* Wb = W + bn * 128;

    float acc[8][8];
#pragma unroll
    for (int i = 0; i < 8; i++)
#pragma unroll
        for (int j = 0; j < 8; j++) acc[i][j] = 0.f;

    for (int k0 = 0; k0 < D_; k0 += 8) {
        float4 a = *(const float4*)(Xb + (size_t)aRow * D_ + k0 + aCol);
        float4 b = *(const float4*)(Wb + (size_t)(k0 + wRow) * U_ + wCol);
        __syncthreads();
        As[aCol + 0][aRow] = a.x;
        As[aCol + 1][aRow] = a.y;
        As[aCol + 2][aRow] = a.z;
        As[aCol + 3][aRow] = a.w;
        *(float4*)&Bs[wRow][wCol] = b;
        __syncthreads();
#pragma unroll
        for (int kk = 0; kk < 8; kk++) {
            float am[8], bw[8];
            *(float4*)&am[0] = *(const float4*)&As[kk][ty * 8];
            *(float4*)&am[4] = *(const float4*)&As[kk][ty * 8 + 4];
            *(float4*)&bw[0] = *(const float4*)&Bs[kk][tx * 8];
            *(float4*)&bw[4] = *(const float4*)&Bs[kk][tx * 8 + 4];
#pragma unroll
            for (int i = 0; i < 8; i++)
#pragma unroll
                for (int j = 0; j < 8; j++) acc[i][j] += am[i] * bw[j];
        }
    }

    const int ncol = bn * 128 + tx * 8;
    float bia[8];
#pragma unroll
    for (int j = 0; j < 8; j++) bia[j] = bias[ncol + j];
#pragma unroll
    for (int i = 0; i < 8; i++) {
        const int m = bm * 128 + ty * 8 + i;
        float4 v0, v1;
        v0.x = acc[i][0] + bia[0];
        v0.y = acc[i][1] + bia[1];
        v0.z = acc[i][2] + bia[2];
        v0.w = acc[i][3] + bia[3];
        v1.x = acc[i][4] + bia[4];
        v1.y = acc[i][5] + bia[5];
        v1.z = acc[i][6] + bia[6];
        v1.w = acc[i][7] + bia[7];
        *(float4*)&g_xproj[(size_t)m * U_ + ncol] = v0;
        *(float4*)&g_xproj[(size_t)m * U_ + ncol + 4] = v1;
    }
}

// =====================================================================
// Kernel 2: the scan. 128 CTAs = 16 row-blocks (8 batch rows) x 8
// col-blocks (64 cols). Each CTA keeps its w_rec[64k x 2c per thread]
// slice in REGISTERS; h rows live in smem, refreshed from L2 each step.
// Per-rowblock (8-CTA) software barriers; 2 per step.
// =====================================================================
__global__ void __launch_bounds__(256, 1) liquid_scan(const float* __restrict__ wrec,
                                                      const float* __restrict__ tau,
                                                      const float* __restrict__ gamma,
                                                      const float* __restrict__ beta,
                                                      float* __restrict__ out) {
    __shared__ float sH[8 * U_];          // [r][k] current h rows, 16 KB
    __shared__ float sPart[8 * 8 * 64];   // [warp(k-split)][r][c], 16 KB
    __shared__ float sNS[8 * 64];         // [r][c] new_state tile, 2 KB

    const int tid = threadIdx.x;
    const int lane = tid & 31;
    const int warp = tid >> 5;            // 0..7 : K split (64 k each)
    const int bblk = blockIdx.x >> 3;     // 0..15
    const int cblk = blockIdx.x & 7;      // 0..7
    const int rb = bblk * 8;
    const int cb = cblk * 64;
    const int c0 = lane * 2;              // thread's 2 cols within [0,64)

    // preload this thread's w_rec slice: k in [warp*64, warp*64+64), cols cb+c0..+1
    float2 wreg[64];
    {
        const int kb = warp * 64;
#pragma unroll
        for (int i = 0; i < 64; i++)
            wreg[i] = *(const float2*)&wrec[(size_t)(kb + i) * U_ + cb + c0];
    }
    const float2 tau2 = *(const float2*)&tau[cb + c0];
    const float2 gam2 = *(const float2*)&gamma[cb + c0];
    const float2 bet2 = *(const float2*)&beta[cb + c0];

    const int r_red = warp;  // reduce/LN phase: warp <-> row
    int nbar = 0;

    for (int t = 0; t < T_; t++) {
        // ---- refresh h rows from global (L2-coherent; peers wrote them) ----
        {
            const float4* Hg = (const float4*)g_H;
#pragma unroll
            for (int i = 0; i < 4; i++) {
                const int idx = tid + i * 256;     // 0..1023 over [8][128] float4
                const int r = idx >> 7;
                const int k4 = idx & 127;
                float4 v = __ldcg(&Hg[(size_t)(rb + r) * 128 + k4]);
                *(float4*)&sH[r * U_ + k4 * 4] = v;
            }
        }
        __syncthreads();

        // ---- partial GEMM: acc[r] += h[r, kslice] . wreg ----
        float2 acc[8];
#pragma unroll
        for (int r = 0; r < 8; r++) acc[r] = make_float2(0.f, 0.f);
        {
            const float4* sH4 = (const float4*)sH;
            const int kb4 = warp * 16;
#pragma unroll
            for (int i4 = 0; i4 < 16; i4++) {
                float4 h[8];
#pragma unroll
                for (int r = 0; r < 8; r++) h[r] = sH4[r * 128 + kb4 + i4];  // broadcast
#pragma unroll
                for (int kk = 0; kk < 4; kk++) {
                    const float2 wv = wreg[i4 * 4 + kk];
#pragma unroll
                    for (int r = 0; r < 8; r++) {
                        const float hv = ((const float*)&h[r])[kk];
                        acc[r].x += hv * wv.x;
                        acc[r].y += hv * wv.y;
                    }
                }
            }
        }
#pragma unroll
        for (int r = 0; r < 8; r++)
            *(float2*)&sPart[(warp * 8 + r) * 64 + c0] = acc[r];
        __syncthreads();

        // ---- K-reduction + liquid update + LN partials (warp r_red owns row) ----
        {
            float2 red = make_float2(0.f, 0.f);
#pragma unroll
            for (int w = 0; w < 8; w++) {
                const float2 p = *(const float2*)&sPart[(w * 8 + r_red) * 64 + c0];
                red.x += p.x;
                red.y += p.y;
            }
            const int b = rb + r_red;
            const float2 xp = *(const float2*)&g_xproj[((size_t)b * T_ + t) * U_ + cb + c0];
            const float base0 = red.x + xp.x;
            const float base1 = red.y + xp.y;
            const float h0 = sH[r_red * U_ + cb + c0];
            const float h1 = sH[r_red * U_ + cb + c0 + 1];
            const float sg0 = 1.f / (1.f + __expf(-base0));
            const float sg1 = 1.f / (1.f + __expf(-base1));
            const float lt0 = tau2.x * sg0 + 1e-7f;
            const float lt1 = tau2.y * sg1 + 1e-7f;
            const float ns0 = h0 + (base0 - h0) * lt0;
            const float ns1 = h1 + (base1 - h1) * lt1;
            float s = ns0 + ns1;
            float q = ns0 * ns0 + ns1 * ns1;
#pragma unroll
            for (int o = 16; o > 0; o >>= 1) {
                s += __shfl_xor_sync(0xffffffffu, s, o);
                q += __shfl_xor_sync(0xffffffffu, q, o);
            }
            if (lane == 0) {
                g_psum[b * 8 + cblk] = s;
                g_psq[b * 8 + cblk] = q;
            }
            sNS[r_red * 64 + c0] = ns0;
            sNS[r_red * 64 + c0 + 1] = ns1;
        }

        // ---- barrier 1 (all 8 col-block CTAs of this row-block) ----
        __threadfence();
        __syncthreads();
        nbar++;
        if (tid == 0) {
            atomicAdd(&g_bar[bblk], 1);
            while (*(volatile int*)&g_bar[bblk] < 8 * nbar) { }
        }
        __syncthreads();

        // ---- finalize LayerNorm, write new h ----
        {
            const int b = rb + r_red;
            float s = 0.f, q = 0.f;
            if (lane < 8) {
                s = __ldcg(&g_psum[b * 8 + lane]);
                q = __ldcg(&g_psq[b * 8 + lane]);
            }
#pragma unroll
            for (int o = 4; o > 0; o >>= 1) {
                s += __shfl_xor_sync(0xffffffffu, s, o);
                q += __shfl_xor_sync(0xffffffffu, q, o);
            }
            s = __shfl_sync(0xffffffffu, s, 0);
            q = __shfl_sync(0xffffffffu, q, 0);
            const float mean = s * (1.f / 512.f);
            const float var = q * (1.f / 512.f) - mean * mean;
            const float rstd = rsqrtf(var + 1e-3f);
            const float ns0 = sNS[r_red * 64 + c0];
            const float ns1 = sNS[r_red * 64 + c0 + 1];
            float2 hv;
            hv.x = gam2.x * (ns0 - mean) * rstd + bet2.x;
            hv.y = gam2.y * (ns1 - mean) * rstd + bet2.y;
            *(float2*)&g_H[(size_t)b * U_ + cb + c0] = hv;
            if (t == T_ - 1)
                *(float2*)&out[(size_t)b * U_ + cb + c0] = hv;
        }

        // ---- barrier 2 (protects next step's h reload) ----
        __threadfence();
        __syncthreads();
        nbar++;
        if (tid == 0) {
            atomicAdd(&g_bar[bblk], 1);
            while (*(volatile int*)&g_bar[bblk] < 8 * nbar) { }
        }
        __syncthreads();
    }
}

// =====================================================================
extern "C" void kernel_launch(void* const* d_in, const int* in_sizes, int n_in,
                              void* d_out, int out_size) {
    const float* x     = (const float*)d_in[0];
    const float* w_in  = (const float*)d_in[1];
    const float* w_rec = (const float*)d_in[2];
    const float* bias  = (const float*)d_in[3];
    const float* tau   = (const float*)d_in[4];
    const float* gamma = (const float*)d_in[5];
    const float* beta  = (const float*)d_in[6];
    float* out = (float*)d_out;

    void* pH = nullptr;
    void* pBar = nullptr;
    cudaGetSymbolAddress(&pH, g_H);
    cudaGetSymbolAddress(&pBar, g_bar);
    cudaMemsetAsync(pH, 0, sizeof(float) * B_ * U_);
    cudaMemsetAsync(pBar, 0, sizeof(int) * 16);

    dim3 ggrid(4, 128);
    gemm_xproj<<<ggrid, 256>>>(x, w_in, bias);
    liquid_scan<<<128, 256>>>(w_rec, tau, gamma, beta, out);
}

// round 4
// speedup vs baseline: 1.8225x; 1.8225x over previous
#include <cuda_runtime.h>
#include <cuda_bf16.h>
#include <cstdint>

#define B_ 128
#define T_ 128
#define D_ 2048
#define U_ 512

// ================= device scratch =================
__device__ float g_xproj[(size_t)B_ * T_ * U_];          // 32 MB
__device__ float g_H[2][B_ * U_];                        // ping-pong pre-normalized state
__device__ float g_psum[2][B_ * 8];
__device__ float g_psq[2][B_ * 8];
__device__ int   g_bar[16];
// bf16 hi/lo planes for the tensor-core GEMM
__device__ __nv_bfloat16 g_Ahi[(size_t)16384 * 2048];    // 64 MB
__device__ __nv_bfloat16 g_Alo[(size_t)16384 * 2048];    // 64 MB
__device__ __nv_bfloat16 g_Bhi[(size_t)512 * 2048];      // 2 MB (w_in^T)
__device__ __nv_bfloat16 g_Blo[(size_t)512 * 2048];      // 2 MB

// ================= helpers =================
__device__ __forceinline__ uint32_t smem_u32(const void* p) {
    uint32_t a;
    asm("{ .reg .u64 t; cvta.to.shared.u64 t, %1; cvt.u32.u64 %0, t; }" : "=r"(a) : "l"(p));
    return a;
}
__device__ __forceinline__ void cp_async16(uint32_t dst, const void* src) {
    asm volatile("cp.async.cg.shared.global [%0], [%1], 16;" :: "r"(dst), "l"(src) : "memory");
}
__device__ __forceinline__ void ldmatrix_x4(uint32_t& d0, uint32_t& d1, uint32_t& d2, uint32_t& d3,
                                            uint32_t addr) {
    asm volatile("ldmatrix.sync.aligned.m8n8.x4.shared.b16 {%0,%1,%2,%3}, [%4];"
                 : "=r"(d0), "=r"(d1), "=r"(d2), "=r"(d3) : "r"(addr));
}
__device__ __forceinline__ void mma16816(float* c, const uint32_t* a, const uint32_t* b) {
    asm volatile("mma.sync.aligned.m16n8k16.row.col.f32.bf16.bf16.f32 "
                 "{%0,%1,%2,%3}, {%4,%5,%6,%7}, {%8,%9}, {%0,%1,%2,%3};"
                 : "+f"(c[0]), "+f"(c[1]), "+f"(c[2]), "+f"(c[3])
                 : "r"(a[0]), "r"(a[1]), "r"(a[2]), "r"(a[3]), "r"(b[0]), "r"(b[1]));
}

// ================= conv: x -> hi/lo bf16 planes (row-major, K=2048) =================
__global__ void __launch_bounds__(256) conv_x(const float* __restrict__ x) {
    const size_t i = (size_t)blockIdx.x * 256 + threadIdx.x;
    const size_t e0 = i * 8;
    float4 v0 = *(const float4*)(x + e0);
    float4 v1 = *(const float4*)(x + e0 + 4);
    float v[8] = {v0.x, v0.y, v0.z, v0.w, v1.x, v1.y, v1.z, v1.w};
    unsigned short hs[8], ls[8];
#pragma unroll
    for (int j = 0; j < 8; j++) {
        __nv_bfloat16 h = __float2bfloat16(v[j]);
        __nv_bfloat16 l = __float2bfloat16(v[j] - __bfloat162float(h));
        hs[j] = __bfloat16_as_ushort(h);
        ls[j] = __bfloat16_as_ushort(l);
    }
    uint4 ph, pl;
    ph.x = hs[0] | ((uint32_t)hs[1] << 16); ph.y = hs[2] | ((uint32_t)hs[3] << 16);
    ph.z = hs[4] | ((uint32_t)hs[5] << 16); ph.w = hs[6] | ((uint32_t)hs[7] << 16);
    pl.x = ls[0] | ((uint32_t)ls[1] << 16); pl.y = ls[2] | ((uint32_t)ls[3] << 16);
    pl.z = ls[4] | ((uint32_t)ls[5] << 16); pl.w = ls[6] | ((uint32_t)ls[7] << 16);
    *(uint4*)(g_Ahi + e0) = ph;
    *(uint4*)(g_Alo + e0) = pl;
}

// ================= conv: w_in [2048][512] -> w^T hi/lo [512][2048] =================
__global__ void __launch_bounds__(256) conv_w(const float* __restrict__ w) {
    __shared__ float ts[32][33];
    const int tid = threadIdx.x;
    const int bu = blockIdx.x;   // u tile (16)
    const int bd = blockIdx.y;   // d tile (64)
    const int tx = tid & 31, ty = tid >> 5;
#pragma unroll
    for (int j = 0; j < 4; j++) {
        const int dl = ty + 8 * j;
        ts[dl][tx] = w[(size_t)(bd * 32 + dl) * U_ + bu * 32 + tx];
    }
    __syncthreads();
    const int ul = tid >> 3, kg = (tid & 7) * 4;
    const int u = bu * 32 + ul;
    const int kk = bd * 32 + kg;
    unsigned short hs[4], ls[4];
#pragma unroll
    for (int j = 0; j < 4; j++) {
        const float vv = ts[kg + j][ul];
        __nv_bfloat16 h = __float2bfloat16(vv);
        __nv_bfloat16 l = __float2bfloat16(vv - __bfloat162float(h));
        hs[j] = __bfloat16_as_ushort(h);
        ls[j] = __bfloat16_as_ushort(l);
    }
    uint2 ph, pl;
    ph.x = hs[0] | ((uint32_t)hs[1] << 16); ph.y = hs[2] | ((uint32_t)hs[3] << 16);
    pl.x = ls[0] | ((uint32_t)ls[1] << 16); pl.y = ls[2] | ((uint32_t)ls[3] << 16);
    *(uint2*)(g_Bhi + (size_t)u * D_ + kk) = ph;
    *(uint2*)(g_Blo + (size_t)u * D_ + kk) = pl;
}

// ================= mma.sync GEMM: xproj = X@W + bias =================
// virtual K' = 6144 (seg0: Ahi*Bhi, seg1: Ahi*Blo, seg2: Alo*Bhi)
// CTA 128x128, BK=64, 3 stages of (16KB A + 16KB B), 8 warps @ 32x64
__global__ void __launch_bounds__(256, 2) gemm_mma(const float* __restrict__ bias) {
    extern __shared__ char sm[];
    const uint32_t sb = smem_u32(sm);
    const int tid = threadIdx.x, lane = tid & 31, wid = tid >> 5;
    const int wm = wid & 3, wn = wid >> 2;
    const int bn = blockIdx.x, bm = blockIdx.y;

    float acc[2][8][4];
#pragma unroll
    for (int mi = 0; mi < 2; mi++)
#pragma unroll
        for (int nj = 0; nj < 8; nj++)
#pragma unroll
            for (int e = 0; e < 4; e++) acc[mi][nj][e] = 0.f;

    // precompute per-thread load indices
    const int lr = 0;  // unused
    (void)lr;

    auto load_stage = [&](int s, int kch) {
        const int seg = kch >> 5, ck = kch & 31;
        const __nv_bfloat16* Ab = (seg < 2) ? g_Ahi : g_Alo;
        const __nv_bfloat16* Bb = (seg == 1) ? g_Blo : g_Bhi;
        const uint32_t sA = sb + s * 32768;
        const uint32_t sB = sA + 16384;
#pragma unroll
        for (int i = 0; i < 4; i++) {
            const int cid = tid + 256 * i;
            const int r = cid >> 3, c = cid & 7;
            const uint32_t sw = (uint32_t)((c ^ (r & 7)) << 4);
            cp_async16(sA + r * 128 + sw,
                       Ab + (size_t)(bm * 128 + r) * D_ + ck * 64 + c * 8);
            cp_async16(sB + r * 128 + sw,
                       Bb + (size_t)(bn * 128 + r) * D_ + ck * 64 + c * 8);
        }
    };

    load_stage(0, 0);
    asm volatile("cp.async.commit_group;" ::: "memory");
    load_stage(1, 1);
    asm volatile("cp.async.commit_group;" ::: "memory");

    for (int k = 0; k < 96; k++) {
        asm volatile("cp.async.wait_group 1;" ::: "memory");
        __syncthreads();
        if (k + 2 < 96) load_stage((k + 2) % 3, k + 2);
        asm volatile("cp.async.commit_group;" ::: "memory");

        const uint32_t sA = sb + (k % 3) * 32768;
        const uint32_t sB = sA + 16384;
#pragma unroll
        for (int kk = 0; kk < 4; kk++) {
            uint32_t aF[2][4];
#pragma unroll
            for (int mi = 0; mi < 2; mi++) {
                const int row = wm * 32 + mi * 16 + (lane & 15);
                const int ch = kk * 2 + (lane >> 4);
                ldmatrix_x4(aF[mi][0], aF[mi][1], aF[mi][2], aF[mi][3],
                            sA + row * 128 + ((ch ^ (row & 7)) << 4));
            }
            uint32_t bF[8][2];
#pragma unroll
            for (int ni = 0; ni < 4; ni++) {
                const int row = wn * 64 + ni * 16 + (lane & 7) + ((lane & 16) >> 1);
                const int ch = kk * 2 + ((lane & 8) >> 3);
                uint32_t r0, r1, r2, r3;
                ldmatrix_x4(r0, r1, r2, r3, sB + row * 128 + ((ch ^ (row & 7)) << 4));
                bF[2 * ni][0] = r0; bF[2 * ni][1] = r1;
                bF[2 * ni + 1][0] = r2; bF[2 * ni + 1][1] = r3;
            }
#pragma unroll
            for (int mi = 0; mi < 2; mi++)
#pragma unroll
                for (int nj = 0; nj < 8; nj++)
                    mma16816(acc[mi][nj], aF[mi], bF[nj]);
        }
    }

    // epilogue: add bias, write fp32
#pragma unroll
    for (int mi = 0; mi < 2; mi++) {
        const int row = bm * 128 + wm * 32 + mi * 16 + (lane >> 2);
#pragma unroll
        for (int nj = 0; nj < 8; nj++) {
            const int col = bn * 128 + wn * 64 + nj * 8 + (lane & 3) * 2;
            const float2 bi = *(const float2*)&bias[col];
            float2 v0, v1;
            v0.x = acc[mi][nj][0] + bi.x;
            v0.y = acc[mi][nj][1] + bi.y;
            v1.x = acc[mi][nj][2] + bi.x;
            v1.y = acc[mi][nj][3] + bi.y;
            *(float2*)&g_xproj[(size_t)row * U_ + col] = v0;
            *(float2*)&g_xproj[(size_t)(row + 8) * U_ + col] = v1;
        }
    }
}

// ================= scan: 1 global barrier/step, ping-pong state =================
__global__ void __launch_bounds__(256, 1) liquid_scan(const float* __restrict__ wrec,
                                                      const float* __restrict__ tau,
                                                      const float* __restrict__ gamma,
                                                      const float* __restrict__ beta,
                                                      float* __restrict__ out) {
    __shared__ float sH[8 * U_];
    __shared__ float sPart[8 * 8 * 64];
    __shared__ float sGB[2 * U_];
    __shared__ float sMR[16];

    const int tid = threadIdx.x;
    const int lane = tid & 31;
    const int warp = tid >> 5;
    const int bblk = blockIdx.x >> 3;
    const int cblk = blockIdx.x & 7;
    const int rb = bblk * 8;
    const int cb = cblk * 64;
    const int c0 = lane * 2;

    float2 wreg[64];
    {
        const int kb = warp * 64;
#pragma unroll
        for (int i = 0; i < 64; i++)
            wreg[i] = *(const float2*)&wrec[(size_t)(kb + i) * U_ + cb + c0];
    }
    const float2 tau2 = *(const float2*)&tau[cb + c0];
    const float2 gam2 = *(const float2*)&gamma[cb + c0];
    const float2 bet2 = *(const float2*)&beta[cb + c0];
    for (int i = tid; i < U_; i += 256) {
        sGB[i] = gamma[i];
        sGB[U_ + i] = beta[i];
    }

    const int r_red = warp;
    const int b_own = rb + r_red;
    int nbar = 0;

    for (int t = 0; t < T_; t++) {
        const int pr = t & 1;        // read buffer (state t-1)
        const int pw = pr ^ 1;       // write buffer (state t)

        if (t == 0) {
#pragma unroll
            for (int i = 0; i < 4; i++)
                *(float4*)&sH[(tid + i * 256) * 4] = make_float4(0.f, 0.f, 0.f, 0.f);
        } else {
            const float4* Hg = (const float4*)g_H[pr];
#pragma unroll
            for (int i = 0; i < 4; i++) {
                const int idx = tid + i * 256;
                const int r = idx >> 7;
                const int k4 = idx & 127;
                float4 v = __ldcg(&Hg[(size_t)(rb + r) * 128 + k4]);
                const float m = sMR[r], rs = sMR[8 + r];
                const int c = k4 * 4;
                v.x = sGB[c + 0] * (v.x - m) * rs + sGB[U_ + c + 0];
                v.y = sGB[c + 1] * (v.y - m) * rs + sGB[U_ + c + 1];
                v.z = sGB[c + 2] * (v.z - m) * rs + sGB[U_ + c + 2];
                v.w = sGB[c + 3] * (v.w - m) * rs + sGB[U_ + c + 3];
                *(float4*)&sH[r * U_ + c] = v;
            }
        }
        const float2 xp = *(const float2*)&g_xproj[((size_t)b_own * T_ + t) * U_ + cb + c0];
        __syncthreads();

        // partial GEMM over this warp's 64-k slice
        float2 acc[8];
#pragma unroll
        for (int r = 0; r < 8; r++) acc[r] = make_float2(0.f, 0.f);
        {
            const float4* sH4 = (const float4*)sH;
            const int kb4 = warp * 16;
#pragma unroll
            for (int i4 = 0; i4 < 16; i4++) {
                float4 h[8];
#pragma unroll
                for (int r = 0; r < 8; r++) h[r] = sH4[r * 128 + kb4 + i4];
#pragma unroll
                for (int kkk = 0; kkk < 4; kkk++) {
                    const float2 wv = wreg[i4 * 4 + kkk];
#pragma unroll
                    for (int r = 0; r < 8; r++) {
                        const float hv = ((const float*)&h[r])[kkk];
                        acc[r].x += hv * wv.x;
                        acc[r].y += hv * wv.y;
                    }
                }
            }
        }
#pragma unroll
        for (int r = 0; r < 8; r++)
            *(float2*)&sPart[(warp * 8 + r) * 64 + c0] = acc[r];
        __syncthreads();

        // reduce + liquid update; publish PRE-LN state + LN partials
        float ns0, ns1;
        {
            float2 red = make_float2(0.f, 0.f);
#pragma unroll
            for (int w = 0; w < 8; w++) {
                const float2 p = *(const float2*)&sPart[(w * 8 + r_red) * 64 + c0];
                red.x += p.x;
                red.y += p.y;
            }
            const float base0 = red.x + xp.x;
            const float base1 = red.y + xp.y;
            const float h0 = sH[r_red * U_ + cb + c0];
            const float h1 = sH[r_red * U_ + cb + c0 + 1];
            const float sg0 = 1.f / (1.f + __expf(-base0));
            const float sg1 = 1.f / (1.f + __expf(-base1));
            const float lt0 = tau2.x * sg0 + 1e-7f;
            const float lt1 = tau2.y * sg1 + 1e-7f;
            ns0 = h0 + (base0 - h0) * lt0;
            ns1 = h1 + (base1 - h1) * lt1;
            float s = ns0 + ns1;
            float q = ns0 * ns0 + ns1 * ns1;
#pragma unroll
            for (int o = 16; o > 0; o >>= 1) {
                s += __shfl_xor_sync(0xffffffffu, s, o);
                q += __shfl_xor_sync(0xffffffffu, q, o);
            }
            *(float2*)&g_H[pw][(size_t)b_own * U_ + cb + c0] = make_float2(ns0, ns1);
            if (lane == 0) {
                g_psum[pr][b_own * 8 + cblk] = s;
                g_psq[pr][b_own * 8 + cblk] = q;
            }
        }

        // one global barrier per step
        __threadfence();
        __syncthreads();
        nbar++;
        if (tid == 0) {
            atomicAdd(&g_bar[bblk], 1);
            while (*(volatile int*)&g_bar[bblk] < 8 * nbar) { }
        }
        __syncthreads();

        // mean/rstd for all 8 rows; stash for next step's fused normalize-on-load
        {
            float s = 0.f, q = 0.f;
            if (lane < 8) {
                s = __ldcg(&g_psum[pr][b_own * 8 + lane]);
                q = __ldcg(&g_psq[pr][b_own * 8 + lane]);
            }
#pragma unroll
            for (int o = 4; o > 0; o >>= 1) {
                s += __shfl_xor_sync(0xffffffffu, s, o);
                q += __shfl_xor_sync(0xffffffffu, q, o);
            }
            s = __shfl_sync(0xffffffffu, s, 0);
            q = __shfl_sync(0xffffffffu, q, 0);
            const float mean = s * (1.f / 512.f);
            const float var = q * (1.f / 512.f) - mean * mean;
            const float rstd = rsqrtf(var + 1e-3f);
            if (lane == 0) {
                sMR[r_red] = mean;
                sMR[8 + r_red] = rstd;
            }
            if (t == T_ - 1) {
                float2 hv;
                hv.x = gam2.x * (ns0 - mean) * rstd + bet2.x;
                hv.y = gam2.y * (ns1 - mean) * rstd + bet2.y;
                *(float2*)&out[(size_t)b_own * U_ + cb + c0] = hv;
            }
        }
        __syncthreads();
    }
}

// ================= launch =================
extern "C" void kernel_launch(void* const* d_in, const int* in_sizes, int n_in,
                              void* d_out, int out_size) {
    const float* x     = (const float*)d_in[0];
    const float* w_in  = (const float*)d_in[1];
    const float* w_rec = (const float*)d_in[2];
    const float* bias  = (const float*)d_in[3];
    const float* tau   = (const float*)d_in[4];
    const float* gamma = (const float*)d_in[5];
    const float* beta  = (const float*)d_in[6];
    float* out = (float*)d_out;

    void* pBar = nullptr;
    cudaGetSymbolAddress(&pBar, g_bar);
    cudaMemsetAsync(pBar, 0, sizeof(int) * 16);

    static int smem_set = 0;
    if (!smem_set) {
        cudaFuncSetAttribute(gemm_mma, cudaFuncAttributeMaxDynamicSharedMemorySize, 98304);
        smem_set = 1;
    }

    conv_x<<<16384, 256>>>(x);
    conv_w<<<dim3(16, 64), 256>>>(w_in);
    gemm_mma<<<dim3(4, 128), 256, 98304>>>(bias);
    liquid_scan<<<128, 256>>>(w_rec, tau, gamma, beta, out);
}